// round 5
// baseline (speedup 1.0000x reference)
#include <cuda_runtime.h>
#include <math.h>

// BoundaryLoss: exact squared-EDT via separable min-convolution, all-integer.
// Scratch: 4 packed u32 volumes, field pair (pos|neg<<16) per (b, cls).
// W pass: ballot/clz nearest-zero, packed u32 out.
// H pass: exact windowed integer min-conv on both halves per block.
// D pass: same, fused with softmax + signed-dist + reduction.
// Shapes: B=2, C=3, D=H=W=96.

#define N2 9216           // 96*96
#define N3 884736         // 96^3
#define SENTI 65535
#define THRS 32768        // real values <= 27075 < THRS <= sentinel-derived >= 47485

__device__ unsigned g_pack[4 * N3];   // 14.2 MB packed scratch
__device__ float g_part[1152];
__device__ int   g_cnt[4];
__device__ int   g_is32;

// ------------------------------------------------------------- dtype detect
__global__ void k_detect(const int* __restrict__ t32) {
    if (threadIdx.x < 4) g_cnt[threadIdx.x] = 0;
    int any = 0;
    #pragma unroll
    for (int u = 0; u < 16; u++) {
        int k = threadIdx.x + 256 * u;
        if (t32[2 * k + 1] != 0) any = 1;
    }
    int r = __syncthreads_or(any);
    if (threadIdx.x == 0) g_is32 = r ? 1 : 0;
}

// ------------------------------------------------- fused init + W-axis pass
__device__ __forceinline__ int near_zero_dist(unsigned z0, unsigned z1, unsigned z2,
                                              int w, int r) {
    unsigned lowm = (2u << r) - 1u;
    unsigned him  = 0xffffffffu << r;
    int dl = 1000, dr = 1000;
    if (w == 0) {
        unsigned u = z0 & lowm;
        if (u) dl = r - (31 - __clz(u));
        unsigned v = z0 & him;
        if (v)       dr = (__ffs(v) - 1) - r;
        else if (z1) dr = 32 - r + (__ffs(z1) - 1);
        else if (z2) dr = 64 - r + (__ffs(z2) - 1);
    } else if (w == 1) {
        unsigned u = z1 & lowm;
        if (u)       dl = r - (31 - __clz(u));
        else if (z0) dl = r + 1 + __clz(z0);
        unsigned v = z1 & him;
        if (v)       dr = (__ffs(v) - 1) - r;
        else if (z2) dr = 32 - r + (__ffs(z2) - 1);
    } else {
        unsigned u = z2 & lowm;
        if (u)       dl = r - (31 - __clz(u));
        else if (z1) dl = r + 1 + __clz(z1);
        else if (z0) dl = r + 33 + __clz(z0);
        unsigned v = z2 & him;
        if (v) dr = (__ffs(v) - 1) - r;
    }
    return min(dl, dr);
}

__device__ __forceinline__ unsigned enc_d(int d) {
    return (d > 95) ? (unsigned)SENTI : (unsigned)(d * d);
}

__global__ void __launch_bounds__(256) k_binw(const void* __restrict__ tptr) {
    int wid = threadIdx.x >> 5, l = threadIdx.x & 31;
    int L = blockIdx.x * 8 + wid;
    int b = L / 9216;
    int n = L - b * 9216;
    int base = b * N3 + n * 96;

    int t0, t1, t2;
    if (g_is32) {
        const int* T = (const int*)tptr;
        t0 = T[base + l]; t1 = T[base + l + 32]; t2 = T[base + l + 64];
    } else {
        const long long* T = (const long long*)tptr;
        t0 = (int)T[base + l]; t1 = (int)T[base + l + 32]; t2 = (int)T[base + l + 64];
    }
    unsigned m1_0 = __ballot_sync(0xffffffffu, t0 == 1);
    unsigned m1_1 = __ballot_sync(0xffffffffu, t1 == 1);
    unsigned m1_2 = __ballot_sync(0xffffffffu, t2 == 1);
    unsigned m2_0 = __ballot_sync(0xffffffffu, t0 == 2);
    unsigned m2_1 = __ballot_sync(0xffffffffu, t1 == 2);
    unsigned m2_2 = __ballot_sync(0xffffffffu, t2 == 2);

    __shared__ int sc[2];
    if (threadIdx.x < 2) sc[threadIdx.x] = 0;
    __syncthreads();
    if (l == 0) {
        atomicAdd(&sc[0], __popc(m1_0) + __popc(m1_1) + __popc(m1_2));
        atomicAdd(&sc[1], __popc(m2_0) + __popc(m2_1) + __popc(m2_2));
    }
    __syncthreads();
    if (threadIdx.x == 0) {
        atomicAdd(&g_cnt[b * 2 + 0], sc[0]);
        atomicAdd(&g_cnt[b * 2 + 1], sc[1]);
    }

    #pragma unroll
    for (int cls = 0; cls < 2; cls++) {
        unsigned m0 = cls ? m2_0 : m1_0;
        unsigned m1 = cls ? m2_1 : m1_1;
        unsigned m2 = cls ? m2_2 : m1_2;
        // pos field (low16): zeros where mask False -> z = ~m
        // neg field (high16): zeros where mask True -> z = m
        unsigned* out = g_pack + (size_t)(b * 2 + cls) * N3 + n * 96;
        #pragma unroll
        for (int w = 0; w < 3; w++) {
            int dp = near_zero_dist(~m0, ~m1, ~m2, w, l);
            int dn = near_zero_dist(m0, m1, m2, w, l);
            out[l + 32 * w] = enc_d(dp) | (enc_d(dn) << 16);
        }
    }
}

// ------------------------------------------------- window radius from max
__device__ __forceinline__ int win_i(int m) {
    if (m >= SENTI) return 95;
    return min(95, (int)floorf(sqrtf((float)m)) + 1);
}

// ------------------------------------------------- integer packed min-conv
// v0/v1[k] = min_j (lo/hi(sp[j]) + m2j*ik[k]) over j in [j0, j1].
__device__ __forceinline__ void minconv2x12(const unsigned* __restrict__ spp,
                                            int j0, int j1, const int ik[12],
                                            int v0[12], int v1[12]) {
    int m2a = -2 * j0;
    int j = j0;
    for (; j + 1 <= j1; j += 2) {
        unsigned ua = spp[j * 32];
        unsigned ub = spp[j * 32 + 32];
        int loa = (int)(ua & 0xffffu), hia = (int)(ua >> 16);
        int lob = (int)(ub & 0xffffu), hib = (int)(ub >> 16);
        int m2b = m2a - 2;
        #pragma unroll
        for (int k = 0; k < 12; k++) {
            int ta = m2a * ik[k];
            int tb = m2b * ik[k];
            v0[k] = min(v0[k], loa + ta);
            v1[k] = min(v1[k], hia + ta);
            v0[k] = min(v0[k], lob + tb);
            v1[k] = min(v1[k], hib + tb);
        }
        m2a -= 4;
    }
    if (j == j1) {
        unsigned ua = spp[j * 32];
        int loa = (int)(ua & 0xffffu), hia = (int)(ua >> 16);
        #pragma unroll
        for (int k = 0; k < 12; k++) {
            int ta = m2a * ik[k];
            v0[k] = min(v0[k], loa + ta);
            v1[k] = min(v1[k], hia + ta);
        }
    }
}

// ---------------------------------------------------------------- H pass
// Grid: 4 packed vols * 96 d-slices * 3 w-chunks = 1152 blocks x 256.
__global__ void __launch_bounds__(256) k_pass_h() {
    __shared__ unsigned sp[96 * 32];
    __shared__ int smx0, smx1;
    int bid = blockIdx.x;
    int vb = bid / 288, rem = bid % 288;
    int s = rem / 3, wc = rem % 3;
    size_t base = (size_t)vb * N3 + (size_t)s * N2 + wc * 32;
    int tx = threadIdx.x & 31, ty = threadIdx.x >> 5;

    if (threadIdx.x == 0) { smx0 = 0; smx1 = 0; }
    __syncthreads();
    int mx0 = 0, mx1 = 0;
    #pragma unroll
    for (int r = ty; r < 96; r += 8) {
        unsigned u = g_pack[base + r * 96 + tx];
        int lo = (int)(u & 0xffffu), hi = (int)(u >> 16);
        mx0 = max(mx0, lo); mx1 = max(mx1, hi);
        int r2 = r * r;
        unsigned plo = (unsigned)min(lo + r2, SENTI);
        unsigned phi = (unsigned)min(hi + r2, SENTI);
        sp[r * 32 + tx] = plo | (phi << 16);
    }
    #pragma unroll
    for (int off = 16; off; off >>= 1) {
        mx0 = max(mx0, __shfl_xor_sync(0xffffffffu, mx0, off));
        mx1 = max(mx1, __shfl_xor_sync(0xffffffffu, mx1, off));
    }
    if (tx == 0) { atomicMax(&smx0, mx0); atomicMax(&smx1, mx1); }
    __syncthreads();
    int R = max(win_i(smx0), win_i(smx1));

    int i0 = ty * 12;
    int j0 = max(0, i0 - R), j1 = min(95, i0 + 11 + R);
    int v0[12], v1[12], ik[12];
    #pragma unroll
    for (int k = 0; k < 12; k++) { v0[k] = 0x3fffffff; v1[k] = 0x3fffffff; ik[k] = i0 + k; }
    minconv2x12(sp + tx, j0, j1, ik, v0, v1);

    unsigned* outp = g_pack + base + (size_t)i0 * 96 + tx;
    #pragma unroll
    for (int k = 0; k < 12; k++) {
        int i2 = ik[k] * ik[k];
        int r0 = v0[k] + i2;
        int r1 = v1[k] + i2;
        unsigned e0 = (r0 >= THRS) ? (unsigned)SENTI : (unsigned)r0;
        unsigned e1 = (r1 >= THRS) ? (unsigned)SENTI : (unsigned)r1;
        outp[k * 96] = e0 | (e1 << 16);
    }
}

// ------------------------------------------- fused D pass + softmax reduce
// Grid: 4 packed vols (b,cls) * 96 h-slices * 3 w-chunks = 1152 blocks x 256.
__global__ void __launch_bounds__(256) k_fuse_d(const float* __restrict__ logits) {
    __shared__ unsigned sp[96 * 32];
    __shared__ int smx0, smx1;
    __shared__ float swred[8];
    int bid = blockIdx.x;
    int vb = bid / 288, rem = bid % 288;
    int s = rem / 3, wc = rem % 3;
    int b = vb >> 1, cls = vb & 1;
    int tx = threadIdx.x & 31, ty = threadIdx.x >> 5;
    unsigned nbase = (unsigned)s * 96 + wc * 32 + tx;   // voxel idx: + d*N2

    if (threadIdx.x == 0) { smx0 = 0; smx1 = 0; }
    __syncthreads();

    const unsigned* p = g_pack + (size_t)vb * N3 + nbase;
    int mx0 = 0, mx1 = 0;
    #pragma unroll
    for (int r = ty; r < 96; r += 8) {
        unsigned u = p[(size_t)r * N2];
        int lo = (int)(u & 0xffffu), hi = (int)(u >> 16);
        mx0 = max(mx0, lo); mx1 = max(mx1, hi);
        int r2 = r * r;
        unsigned plo = (unsigned)min(lo + r2, SENTI);
        unsigned phi = (unsigned)min(hi + r2, SENTI);
        sp[r * 32 + tx] = plo | (phi << 16);
    }
    #pragma unroll
    for (int off = 16; off; off >>= 1) {
        mx0 = max(mx0, __shfl_xor_sync(0xffffffffu, mx0, off));
        mx1 = max(mx1, __shfl_xor_sync(0xffffffffu, mx1, off));
    }
    if (tx == 0) { atomicMax(&smx0, mx0); atomicMax(&smx1, mx1); }
    __syncthreads();
    int R = max(win_i(smx0), win_i(smx1));

    int i0 = ty * 12;
    int j0 = max(0, i0 - R), j1 = min(95, i0 + 11 + R);
    int v0[12], v1[12], ik[12];
    #pragma unroll
    for (int k = 0; k < 12; k++) { v0[k] = 0x3fffffff; v1[k] = 0x3fffffff; ik[k] = i0 + k; }
    minconv2x12(sp + tx, j0, j1, ik, v0, v1);

    // epilogue: sd = sqrt(neg) - sqrt(pos); softmax prob of this class; gate
    float gate = g_cnt[b * 2 + cls] > 0 ? 1.f : 0.f;
    const float* L = logits + (size_t)b * 3 * N3 + nbase + (size_t)i0 * N2;
    float acc = 0.f;
    #pragma unroll
    for (int k = 0; k < 12; k++) {
        int i2 = ik[k] * ik[k];
        int r0 = v0[k] + i2;
        int r1 = v1[k] + i2;
        float f0 = (r0 >= THRS) ? 1e8f : (float)r0;
        float f1 = (r1 >= THRS) ? 1e8f : (float)r1;
        float sd = sqrtf(f1) - sqrtf(f0);
        float l0 = L[0], l1 = L[(size_t)N3], l2 = L[(size_t)2 * N3];
        L += N2;
        float m = fmaxf(l0, fmaxf(l1, l2));
        float e0 = __expf(l0 - m), e1 = __expf(l1 - m), e2 = __expf(l2 - m);
        float ec = cls ? e2 : e1;
        acc += (ec / (e0 + e1 + e2)) * sd;
    }
    acc *= gate;

    #pragma unroll
    for (int off = 16; off; off >>= 1)
        acc += __shfl_down_sync(0xffffffffu, acc, off);
    if (tx == 0) swred[ty] = acc;
    __syncthreads();
    if (threadIdx.x == 0) {
        float t = 0.f;
        #pragma unroll
        for (int i = 0; i < 8; i++) t += swred[i];
        g_part[bid] = t;
    }
}

// ---------------------------------------------------------------- final
__global__ void k_final(float* __restrict__ out) {
    __shared__ double sm[256];
    double s = 0.0;
    for (int i = threadIdx.x; i < 1152; i += 256) s += (double)g_part[i];
    sm[threadIdx.x] = s;
    __syncthreads();
    #pragma unroll
    for (int off = 128; off > 0; off >>= 1) {
        if (threadIdx.x < off) sm[threadIdx.x] += sm[threadIdx.x + off];
        __syncthreads();
    }
    if (threadIdx.x == 0)
        out[0] = (float)(sm[0] / (2.0 * (double)N3));
}

// ---------------------------------------------------------------- launch
extern "C" void kernel_launch(void* const* d_in, const int* in_sizes, int n_in,
                              void* d_out, int out_size) {
    const float* logits = (const float*)d_in[0];
    const void*  targets = d_in[1];
    float* out = (float*)d_out;
    (void)in_sizes; (void)n_in; (void)out_size;

    k_detect<<<1, 256>>>((const int*)targets);
    k_binw<<<2304, 256>>>(targets);
    k_pass_h<<<1152, 256>>>();
    k_fuse_d<<<1152, 256>>>(logits);
    k_final<<<1, 256>>>(out);
}

// round 6
// speedup vs baseline: 1.1788x; 1.1788x over previous
#include <cuda_runtime.h>
#include <math.h>

// BoundaryLoss: exact squared-EDT via separable min-convolution.
// Storage: packed u32 (pos|neg<<16) per (b,cls) — half DRAM traffic.
// Math: float FFMA/FMNMX min-conv (balanced fma/alu pipes) on unpacked
// float smem tiles. 512-thr blocks, 6 outputs/thread for 75% occupancy.
// Shapes: B=2, C=3, D=H=W=96.

#define N2 9216           // 96*96
#define N3 884736         // 96^3
#define SENTI 65535
#define THRSF 32768.0f    // real <= 18050 < 32768 <= sentinel-derived >= 65535

__device__ unsigned g_pack[4 * N3];   // 14.2 MB packed scratch
__device__ float g_part[1152];
__device__ int   g_cnt[4];
__device__ int   g_is32;

// ------------------------------------------------------------- dtype detect
__global__ void k_detect(const int* __restrict__ t32) {
    if (threadIdx.x < 4) g_cnt[threadIdx.x] = 0;
    int any = 0;
    #pragma unroll
    for (int u = 0; u < 16; u++) {
        int k = threadIdx.x + 256 * u;
        if (t32[2 * k + 1] != 0) any = 1;
    }
    int r = __syncthreads_or(any);
    if (threadIdx.x == 0) g_is32 = r ? 1 : 0;
}

// ------------------------------------------------- fused init + W-axis pass
__device__ __forceinline__ int near_zero_dist(unsigned z0, unsigned z1, unsigned z2,
                                              int w, int r) {
    unsigned lowm = (2u << r) - 1u;
    unsigned him  = 0xffffffffu << r;
    int dl = 1000, dr = 1000;
    if (w == 0) {
        unsigned u = z0 & lowm;
        if (u) dl = r - (31 - __clz(u));
        unsigned v = z0 & him;
        if (v)       dr = (__ffs(v) - 1) - r;
        else if (z1) dr = 32 - r + (__ffs(z1) - 1);
        else if (z2) dr = 64 - r + (__ffs(z2) - 1);
    } else if (w == 1) {
        unsigned u = z1 & lowm;
        if (u)       dl = r - (31 - __clz(u));
        else if (z0) dl = r + 1 + __clz(z0);
        unsigned v = z1 & him;
        if (v)       dr = (__ffs(v) - 1) - r;
        else if (z2) dr = 32 - r + (__ffs(z2) - 1);
    } else {
        unsigned u = z2 & lowm;
        if (u)       dl = r - (31 - __clz(u));
        else if (z1) dl = r + 1 + __clz(z1);
        else if (z0) dl = r + 33 + __clz(z0);
        unsigned v = z2 & him;
        if (v) dr = (__ffs(v) - 1) - r;
    }
    return min(dl, dr);
}

__device__ __forceinline__ unsigned enc_d(int d) {
    return (d > 95) ? (unsigned)SENTI : (unsigned)(d * d);
}

__global__ void __launch_bounds__(256) k_binw(const void* __restrict__ tptr) {
    int wid = threadIdx.x >> 5, l = threadIdx.x & 31;
    int L = blockIdx.x * 8 + wid;
    int b = L / 9216;
    int n = L - b * 9216;
    int base = b * N3 + n * 96;

    int t0, t1, t2;
    if (g_is32) {
        const int* T = (const int*)tptr;
        t0 = T[base + l]; t1 = T[base + l + 32]; t2 = T[base + l + 64];
    } else {
        const long long* T = (const long long*)tptr;
        t0 = (int)T[base + l]; t1 = (int)T[base + l + 32]; t2 = (int)T[base + l + 64];
    }
    unsigned m1_0 = __ballot_sync(0xffffffffu, t0 == 1);
    unsigned m1_1 = __ballot_sync(0xffffffffu, t1 == 1);
    unsigned m1_2 = __ballot_sync(0xffffffffu, t2 == 1);
    unsigned m2_0 = __ballot_sync(0xffffffffu, t0 == 2);
    unsigned m2_1 = __ballot_sync(0xffffffffu, t1 == 2);
    unsigned m2_2 = __ballot_sync(0xffffffffu, t2 == 2);

    __shared__ int sc[2];
    if (threadIdx.x < 2) sc[threadIdx.x] = 0;
    __syncthreads();
    if (l == 0) {
        atomicAdd(&sc[0], __popc(m1_0) + __popc(m1_1) + __popc(m1_2));
        atomicAdd(&sc[1], __popc(m2_0) + __popc(m2_1) + __popc(m2_2));
    }
    __syncthreads();
    if (threadIdx.x == 0) {
        atomicAdd(&g_cnt[b * 2 + 0], sc[0]);
        atomicAdd(&g_cnt[b * 2 + 1], sc[1]);
    }

    #pragma unroll
    for (int cls = 0; cls < 2; cls++) {
        unsigned m0 = cls ? m2_0 : m1_0;
        unsigned m1 = cls ? m2_1 : m1_1;
        unsigned m2 = cls ? m2_2 : m1_2;
        unsigned* out = g_pack + (size_t)(b * 2 + cls) * N3 + n * 96;
        #pragma unroll
        for (int w = 0; w < 3; w++) {
            int dp = near_zero_dist(~m0, ~m1, ~m2, w, l);
            int dn = near_zero_dist(m0, m1, m2, w, l);
            out[l + 32 * w] = enc_d(dp) | (enc_d(dn) << 16);
        }
    }
}

// ------------------------------------------------- window radius from max
__device__ __forceinline__ int win_i(int m) {
    if (m >= SENTI) return 95;
    return min(95, (int)floorf(sqrtf((float)m)) + 1);
}

// --------------------------------------- float packed min-conv, 6 outputs
// v0/v1[k] = min_j (s0/s1[j] + m2j*fi[k]) ; s tiles hold f[j]+j^2.
__device__ __forceinline__ void minconv2x6(const float* __restrict__ s0,
                                           const float* __restrict__ s1,
                                           int j0, int j1, const float fi[6],
                                           float v0[6], float v1[6]) {
    float m2a = -2.0f * (float)j0;
    int j = j0;
    for (; j + 1 <= j1; j += 2) {
        float a0 = s0[j * 32], a1 = s1[j * 32];
        float b0 = s0[j * 32 + 32], b1 = s1[j * 32 + 32];
        float m2b = m2a - 2.0f;
        #pragma unroll
        for (int k = 0; k < 6; k++) {
            v0[k] = fminf(v0[k], fmaf(m2a, fi[k], a0));
            v1[k] = fminf(v1[k], fmaf(m2a, fi[k], a1));
            v0[k] = fminf(v0[k], fmaf(m2b, fi[k], b0));
            v1[k] = fminf(v1[k], fmaf(m2b, fi[k], b1));
        }
        m2a -= 4.0f;
    }
    if (j == j1) {
        float a0 = s0[j * 32], a1 = s1[j * 32];
        #pragma unroll
        for (int k = 0; k < 6; k++) {
            v0[k] = fminf(v0[k], fmaf(m2a, fi[k], a0));
            v1[k] = fminf(v1[k], fmaf(m2a, fi[k], a1));
        }
    }
}

// ---------------------------------------------------------------- H pass
// Grid: 4 packed vols * 96 d-slices * 3 w-chunks = 1152 blocks x 512.
__global__ void __launch_bounds__(512, 3) k_pass_h() {
    __shared__ float sh0[96 * 32];
    __shared__ float sh1[96 * 32];
    __shared__ int smx0, smx1;
    int bid = blockIdx.x;
    int vb = bid / 288, rem = bid % 288;
    int s = rem / 3, wc = rem % 3;
    size_t base = (size_t)vb * N3 + (size_t)s * N2 + wc * 32;
    int tx = threadIdx.x & 31, ty = threadIdx.x >> 5;   // ty in [0,16)

    if (threadIdx.x == 0) { smx0 = 0; smx1 = 0; }
    __syncthreads();
    int mx0 = 0, mx1 = 0;
    #pragma unroll
    for (int r = ty; r < 96; r += 16) {
        unsigned u = g_pack[base + r * 96 + tx];
        int lo = (int)(u & 0xffffu), hi = (int)(u >> 16);
        mx0 = max(mx0, lo); mx1 = max(mx1, hi);
        float r2 = (float)(r * r);
        sh0[r * 32 + tx] = (float)lo + r2;
        sh1[r * 32 + tx] = (float)hi + r2;
    }
    #pragma unroll
    for (int off = 16; off; off >>= 1) {
        mx0 = max(mx0, __shfl_xor_sync(0xffffffffu, mx0, off));
        mx1 = max(mx1, __shfl_xor_sync(0xffffffffu, mx1, off));
    }
    if (tx == 0) { atomicMax(&smx0, mx0); atomicMax(&smx1, mx1); }
    __syncthreads();
    int R = max(win_i(smx0), win_i(smx1));

    int i0 = ty * 6;
    int j0 = max(0, i0 - R), j1 = min(95, i0 + 5 + R);
    float v0[6], v1[6], fi[6];
    #pragma unroll
    for (int k = 0; k < 6; k++) { v0[k] = 3.0e38f; v1[k] = 3.0e38f; fi[k] = (float)(i0 + k); }
    minconv2x6(sh0 + tx, sh1 + tx, j0, j1, fi, v0, v1);

    unsigned* outp = g_pack + base + (size_t)i0 * 96 + tx;
    #pragma unroll
    for (int k = 0; k < 6; k++) {
        float i2 = fi[k] * fi[k];
        float r0 = v0[k] + i2;
        float r1 = v1[k] + i2;
        unsigned e0 = (r0 >= THRSF) ? (unsigned)SENTI : (unsigned)__float2int_rn(r0);
        unsigned e1 = (r1 >= THRSF) ? (unsigned)SENTI : (unsigned)__float2int_rn(r1);
        outp[k * 96] = e0 | (e1 << 16);
    }
}

// ------------------------------------------- fused D pass + softmax reduce
// Grid: 4 packed vols (b,cls) * 96 h-slices * 3 w-chunks = 1152 blocks x 512.
__global__ void __launch_bounds__(512, 3) k_fuse_d(const float* __restrict__ logits) {
    __shared__ float sh0[96 * 32];
    __shared__ float sh1[96 * 32];
    __shared__ int smx0, smx1;
    __shared__ float swred[16];
    int bid = blockIdx.x;
    int vb = bid / 288, rem = bid % 288;
    int s = rem / 3, wc = rem % 3;
    int b = vb >> 1, cls = vb & 1;
    int tx = threadIdx.x & 31, ty = threadIdx.x >> 5;
    unsigned nbase = (unsigned)s * 96 + wc * 32 + tx;   // voxel idx: + d*N2

    if (threadIdx.x == 0) { smx0 = 0; smx1 = 0; }
    __syncthreads();

    const unsigned* p = g_pack + (size_t)vb * N3 + nbase;
    int mx0 = 0, mx1 = 0;
    #pragma unroll
    for (int r = ty; r < 96; r += 16) {
        unsigned u = p[(size_t)r * N2];
        int lo = (int)(u & 0xffffu), hi = (int)(u >> 16);
        mx0 = max(mx0, lo); mx1 = max(mx1, hi);
        float r2 = (float)(r * r);
        sh0[r * 32 + tx] = (float)lo + r2;
        sh1[r * 32 + tx] = (float)hi + r2;
    }
    #pragma unroll
    for (int off = 16; off; off >>= 1) {
        mx0 = max(mx0, __shfl_xor_sync(0xffffffffu, mx0, off));
        mx1 = max(mx1, __shfl_xor_sync(0xffffffffu, mx1, off));
    }
    if (tx == 0) { atomicMax(&smx0, mx0); atomicMax(&smx1, mx1); }
    __syncthreads();
    int R = max(win_i(smx0), win_i(smx1));

    int i0 = ty * 6;
    int j0 = max(0, i0 - R), j1 = min(95, i0 + 5 + R);
    float v0[6], v1[6], fi[6];
    #pragma unroll
    for (int k = 0; k < 6; k++) { v0[k] = 3.0e38f; v1[k] = 3.0e38f; fi[k] = (float)(i0 + k); }
    minconv2x6(sh0 + tx, sh1 + tx, j0, j1, fi, v0, v1);

    // epilogue: sd = sqrt(neg) - sqrt(pos); softmax prob of this class; gate
    float gate = g_cnt[b * 2 + cls] > 0 ? 1.f : 0.f;
    const float* L = logits + (size_t)b * 3 * N3 + nbase + (size_t)i0 * N2;
    float acc = 0.f;
    #pragma unroll
    for (int k = 0; k < 6; k++) {
        float i2 = fi[k] * fi[k];
        float r0 = v0[k] + i2;
        float r1 = v1[k] + i2;
        float f0 = (r0 >= THRSF) ? 1e8f : r0;
        float f1 = (r1 >= THRSF) ? 1e8f : r1;
        float sd = sqrtf(f1) - sqrtf(f0);
        float l0 = L[0], l1 = L[(size_t)N3], l2 = L[(size_t)2 * N3];
        L += N2;
        float m = fmaxf(l0, fmaxf(l1, l2));
        float e0 = __expf(l0 - m), e1 = __expf(l1 - m), e2 = __expf(l2 - m);
        float ec = cls ? e2 : e1;
        acc += (ec / (e0 + e1 + e2)) * sd;
    }
    acc *= gate;

    #pragma unroll
    for (int off = 16; off; off >>= 1)
        acc += __shfl_down_sync(0xffffffffu, acc, off);
    if (tx == 0) swred[ty] = acc;
    __syncthreads();
    if (threadIdx.x == 0) {
        float t = 0.f;
        #pragma unroll
        for (int i = 0; i < 16; i++) t += swred[i];
        g_part[bid] = t;
    }
}

// ---------------------------------------------------------------- final
__global__ void k_final(float* __restrict__ out) {
    __shared__ double sm[256];
    double s = 0.0;
    for (int i = threadIdx.x; i < 1152; i += 256) s += (double)g_part[i];
    sm[threadIdx.x] = s;
    __syncthreads();
    #pragma unroll
    for (int off = 128; off > 0; off >>= 1) {
        if (threadIdx.x < off) sm[threadIdx.x] += sm[threadIdx.x + off];
        __syncthreads();
    }
    if (threadIdx.x == 0)
        out[0] = (float)(sm[0] / (2.0 * (double)N3));
}

// ---------------------------------------------------------------- launch
extern "C" void kernel_launch(void* const* d_in, const int* in_sizes, int n_in,
                              void* d_out, int out_size) {
    const float* logits = (const float*)d_in[0];
    const void*  targets = d_in[1];
    float* out = (float*)d_out;
    (void)in_sizes; (void)n_in; (void)out_size;

    k_detect<<<1, 256>>>((const int*)targets);
    k_binw<<<2304, 256>>>(targets);
    k_pass_h<<<1152, 512>>>();
    k_fuse_d<<<1152, 512>>>(logits);
    k_final<<<1, 256>>>(out);
}